// round 13
// baseline (speedup 1.0000x reference)
#include <cuda_runtime.h>
#include <cuda_fp16.h>
#include <cstdint>

#define DEV __device__ __forceinline__

// ---------------- problem dims (fixed) ----------------
static constexpr int DIM_B   = 4096;
static constexpr int DIM_IN  = 1024;
static constexpr int DIM_H   = 16384;
static constexpr int DIM_OUT = 3072;

// ---------------- GEMM tiling ----------------
// 2 CTAs/SM: 256 thr, <=128 regs, ~112 KB smem per CTA. Warp tile 32x64.
static constexpr int BM = 128, BN = 128, BK = 64, NST = 3;
static constexpr int NTHR = 256;                       // 8 warps: 4 (M) x 2 (N)
static constexpr int LDT = 72;                         // padded row length (halves)
static constexpr int ABYTES = BM * LDT * 2;            // 18432
static constexpr int BBYTES = BN * LDT * 2;            // 18432
static constexpr int STAGEB = ABYTES + BBYTES;         // 36864
static constexpr int SB_OFF = NST * STAGEB;            // 110592
static constexpr int MB_OFF = SB_OFF + 2 * BN * 4;     // 111616
// mbarrier block: full_A[3][4] | full_B[3][2] | empty_A[3][4] | empty_B[3][2]
static constexpr int SMEM_BYTES = MB_OFF + 288;        // 111904

// ---------------- scratch (device globals; allocation-free) ----------------
__device__ __align__(128) __half g_Xh [(size_t)DIM_B * DIM_IN];
__device__ __align__(128) __half g_W1t[(size_t)DIM_H * DIM_IN];     // [DH, DIN]
__device__ __align__(128) __half g_W2t[(size_t)DIM_OUT * DIM_H];    // [DOUT, DH]
__device__ __align__(128) __half g_H  [(size_t)DIM_B * DIM_H];

// ---------------- PTX helpers (baseline ISA; no sm_103a-only features) -------
DEV uint32_t s2u(const void* p) { return (uint32_t)__cvta_generic_to_shared(p); }

DEV void cp16(uint32_t dst, const void* src) {
    asm volatile("cp.async.cg.shared.global [%0], [%1], 16;" :: "r"(dst), "l"(src));
}
DEV void cp_mbar_arrive(uint32_t mb) {   // bind this thread's prior cp.asyncs to mbarrier
    asm volatile("cp.async.mbarrier.arrive.noinc.shared.b64 [%0];" :: "r"(mb) : "memory");
}
DEV void mbar_init(uint32_t mb, uint32_t cnt) {
    asm volatile("mbarrier.init.shared.b64 [%0], %1;" :: "r"(mb), "r"(cnt) : "memory");
}
DEV void mbar_arrive(uint32_t mb) {
    asm volatile("mbarrier.arrive.shared.b64 _, [%0];" :: "r"(mb) : "memory");
}
DEV void mbar_wait(uint32_t mb, uint32_t parity) {
    asm volatile(
        "{\n\t.reg .pred P;\n"
        "WAITL%=:\n\t"
        "mbarrier.try_wait.parity.acquire.cta.shared::cta.b64 P, [%0], %1;\n\t"
        "@!P bra WAITL%=;\n\t}\n"
        :: "r"(mb), "r"(parity) : "memory");
}

DEV void ldsm4(uint32_t* r, uint32_t a) {
    asm volatile("ldmatrix.sync.aligned.m8n8.x4.shared.b16 {%0,%1,%2,%3}, [%4];"
                 : "=r"(r[0]), "=r"(r[1]), "=r"(r[2]), "=r"(r[3]) : "r"(a));
}

DEV void mma16816(float* c, const uint32_t* a, const uint32_t* b) {
    asm volatile(
        "mma.sync.aligned.m16n8k16.row.col.f32.f16.f16.f32 "
        "{%0,%1,%2,%3}, {%4,%5,%6,%7}, {%8,%9}, {%0,%1,%2,%3};"
        : "+f"(c[0]), "+f"(c[1]), "+f"(c[2]), "+f"(c[3])
        : "r"(a[0]), "r"(a[1]), "r"(a[2]), "r"(a[3]), "r"(b[0]), "r"(b[1]));
}

DEV float tanh_hw(float x) {   // MUFU.TANH (sm_75+ baseline PTX)
    float y;
    asm("tanh.approx.f32 %0, %1;" : "=f"(y) : "f"(x));
    return y;
}

// scale arrives as a 4-byte scalar of unknown dtype (python int 1). Sniff bits.
DEV float load_scale(const float* p) {
    int iv = __float_as_int(*p);
    if (iv > -(1 << 24) && iv < (1 << 24)) return (float)iv;  // int bit pattern
    return __int_as_float(iv);                                 // real float bits
}

// ---------------- prepass: x -> fp16 ----------------
__global__ void cvt_x_kernel(const float* __restrict__ x, __half* __restrict__ o, int nquads) {
    int i = blockIdx.x * blockDim.x + threadIdx.x;
    if (i < nquads) {
        float4 v = *reinterpret_cast<const float4*>(x + (size_t)i * 4);
        reinterpret_cast<__half2*>(o)[2 * i + 0] = __floats2half2_rn(v.x, v.y);
        reinterpret_cast<__half2*>(o)[2 * i + 1] = __floats2half2_rn(v.z, v.w);
    }
}

// ---------------- prepass: ternarize + transpose ----------------
// W,NZ: [K,N] fp32 row-major.  Out[n,k] = tri(W[k,n] - sc*NZ[k,n]) fp16, shape [N,K]
__global__ void tern_t_kernel(const float* __restrict__ W, const float* __restrict__ NZ,
                              const float* __restrict__ scp, __half* __restrict__ Out,
                              int Kd, int Nd) {
    __shared__ __half t[32][33];
    float sc = load_scale(scp);
    int n0 = blockIdx.x * 32, k0 = blockIdx.y * 32;
    int tx = threadIdx.x, ty = threadIdx.y;  // 32 x 8
#pragma unroll
    for (int i = 0; i < 4; i++) {
        int k = ty + i * 8;
        size_t gi = (size_t)(k0 + k) * Nd + n0 + tx;
        float q = W[gi] - sc * NZ[gi];
        float v = (q > 1.0f) ? 1.0f : ((q < -1.0f) ? -1.0f : 0.0f);
        t[tx][k] = __float2half_rn(v);
    }
    __syncthreads();
#pragma unroll
    for (int i = 0; i < 4; i++) {
        int n = ty + i * 8;
        Out[(size_t)(n0 + n) * Kd + k0 + tx] = t[n][tx];
    }
}

// ---------------- per-warp slice loaders (32 rows = 256 x 16B chunks) -------
// Loads 32 consecutive tile rows into the stage at row base `rbase`,
// then binds this thread's cps to mb (full barrier, count=32 per warp).
DEV void load_slice(const __half* __restrict__ G, int K, int grow0,
                    uint32_t slice_smem, int lane, int k0, uint32_t mb) {
#pragma unroll
    for (int i = 0; i < 8; i++) {
        int r = (lane >> 3) + 4 * i;       // 0..31 within slice
        int c = (lane & 7) * 8;
        cp16(slice_smem + (uint32_t)(r * LDT + c) * 2,
             G + (size_t)(grow0 + r) * K + k0 + c);
    }
    cp_mbar_arrive(mb);
}

// ---------------- fused ternary GEMM (slice-grained barriers) ---------------
// A stage: 4 slices of 32 rows.  full_A[s][m] cnt=32 (warp m produces),
//   consumed by warps {m, m+4}; empty_A[s][m] cnt=2.
// B stage: 2 slices of 64 rows.  full_B[s][n] cnt=64 (warps 4+2n,5+2n produce),
//   consumed by warps with wn-group n; empty_B[s][n] cnt=4.
template <bool TANH>
__global__ __launch_bounds__(NTHR, 2) void gemm_tern(
    const __half* __restrict__ A, const __half* __restrict__ Bw,
    const float* __restrict__ sv, const float* __restrict__ bv,
    void* __restrict__ Cout, int Nld, int K) {

    extern __shared__ char smem[];
    uint32_t base = s2u(smem);

    int tid = threadIdx.x, wid = tid >> 5, lane = tid & 31;
    int m0 = blockIdx.y * BM, n0 = blockIdx.x * BN;
    int wm_i = wid & 3;          // consumer M group (A slice index)
    int wn_i = wid >> 2;         // consumer N group (B slice index)
    int wm = wm_i * 32;
    int wn = wn_i * 64;

    uint32_t FA = base + MB_OFF;            // full_A[3][4]
    uint32_t FB = FA + 96;                  // full_B[3][2]
    uint32_t EA = FB + 48;                  // empty_A[3][4]
    uint32_t EB = EA + 96;                  // empty_B[3][2]
#define FA_AT(s, m) (FA + ((s) * 4 + (m)) * 8)
#define FB_AT(s, n) (FB + ((s) * 2 + (n)) * 8)
#define EA_AT(s, m) (EA + ((s) * 4 + (m)) * 8)
#define EB_AT(s, n) (EB + ((s) * 2 + (n)) * 8)

    float* sS = reinterpret_cast<float*>(smem + SB_OFF);
    float* sB = sS + BN;
    for (int i = tid; i < BN; i += NTHR) { sS[i] = sv[n0 + i]; sB[i] = bv[n0 + i]; }

    if (tid == 0) {
#pragma unroll
        for (int s = 0; s < NST; s++) {
#pragma unroll
            for (int m = 0; m < 4; m++) { mbar_init(FA_AT(s, m), 32); mbar_init(EA_AT(s, m), 2); }
#pragma unroll
            for (int n = 0; n < 2; n++) { mbar_init(FB_AT(s, n), 64); mbar_init(EB_AT(s, n), 4); }
        }
    }
    __syncthreads();   // mbarrier init + sS/sB visible

    // producer role: warps 0-3 -> A slice wid; warps 4-7 -> B slice (wid-4)>>1,
    // half (wid-4)&1 (rows 64*nsl + 32*h).
    bool prodA = (wid < 4);
    int p_nsl = (wid - 4) >> 1, p_h = (wid - 4) & 1;
    uint32_t a_slice_off = (uint32_t)(wid * 32 * LDT) * 2;                 // A producer
    uint32_t b_slice_off = (uint32_t)ABYTES + (uint32_t)((p_nsl * 64 + p_h * 32) * LDT) * 2;
    int a_grow0 = m0 + wid * 32;
    int b_grow0 = n0 + p_nsl * 64 + p_h * 32;

    // per-lane ldmatrix byte offsets within a stage (A at +0, B at +ABYTES)
    uint32_t aoff[2];
#pragma unroll
    for (int im = 0; im < 2; im++)
        aoff[im] = (uint32_t)((wm + im * 16 + (lane & 15)) * LDT + (lane >> 4) * 8) * 2;
    uint32_t boff[4];
    {
        int g = lane >> 3;
#pragma unroll
        for (int p = 0; p < 4; p++)
            boff[p] = (uint32_t)(ABYTES) +
                      (uint32_t)((wn + p * 16 + (g >> 1) * 8 + (lane & 7)) * LDT + (g & 1) * 8) * 2;
    }

    const int KT = K / BK;
    // prologue: each warp loads its slice for stages 0 and 1
#pragma unroll
    for (int jt = 0; jt < 2; jt++) {
        uint32_t stg = base + (uint32_t)jt * STAGEB;
        if (prodA) load_slice(A, K, a_grow0, stg + a_slice_off, lane, jt * BK, FA_AT(jt, wid));
        else       load_slice(Bw, K, b_grow0, stg + b_slice_off, lane, jt * BK, FB_AT(jt, p_nsl));
    }

    float acc[2][8][4];
#pragma unroll
    for (int im = 0; im < 2; im++)
#pragma unroll
        for (int in_ = 0; in_ < 8; in_++)
#pragma unroll
            for (int r = 0; r < 4; r++) acc[im][in_][r] = 0.0f;

    for (int it = 0; it < KT; ++it) {
        int si = it - (it / NST) * NST;
        uint32_t pf = (uint32_t)((it / NST) & 1);
        mbar_wait(FA_AT(si, wm_i), pf);    // only THIS warp's slices
        mbar_wait(FB_AT(si, wn_i), pf);
        uint32_t sbase = base + (uint32_t)si * STAGEB;

        // ks=0 fragments
        uint32_t af[2][4], bf[8][2];
#pragma unroll
        for (int im = 0; im < 2; im++)
            ldsm4(af[im], sbase + aoff[im]);
#pragma unroll
        for (int p = 0; p < 4; p++) {
            uint32_t r4[4];
            ldsm4(r4, sbase + boff[p]);
            bf[2 * p][0] = r4[0]; bf[2 * p][1] = r4[1];
            bf[2 * p + 1][0] = r4[2]; bf[2 * p + 1][1] = r4[3];
        }

        // producer block (slice-local wait; in MMA shadow of other warps)
        int jt = it + 2;
        if (jt < KT) {
            int sj = jt - (jt / NST) * NST;
            uint32_t pe = (uint32_t)(((jt / NST) - 1) & 1);
            uint32_t stg = base + (uint32_t)sj * STAGEB;
            if (prodA) {
                if (jt >= NST) mbar_wait(EA_AT(sj, wid), pe);
                load_slice(A, K, a_grow0, stg + a_slice_off, lane, jt * BK, FA_AT(sj, wid));
            } else {
                if (jt >= NST) mbar_wait(EB_AT(sj, p_nsl), pe);
                load_slice(Bw, K, b_grow0, stg + b_slice_off, lane, jt * BK, FB_AT(sj, p_nsl));
            }
        }

#pragma unroll
        for (int im = 0; im < 2; im++)
#pragma unroll
            for (int in_ = 0; in_ < 8; in_++)
                mma16816(acc[im][in_], af[im], bf[in_]);

#pragma unroll
        for (int ks = 1; ks < 4; ks++) {
            uint32_t kb = (uint32_t)(ks * 16 * 2);
#pragma unroll
            for (int im = 0; im < 2; im++)
                ldsm4(af[im], sbase + aoff[im] + kb);
#pragma unroll
            for (int p = 0; p < 4; p++) {
                uint32_t r4[4];
                ldsm4(r4, sbase + boff[p] + kb);
                bf[2 * p][0] = r4[0]; bf[2 * p][1] = r4[1];
                bf[2 * p + 1][0] = r4[2]; bf[2 * p + 1][1] = r4[3];
            }
            if (ks == 3 && lane == 0) {        // this warp's reads of stage done
                mbar_arrive(EA_AT(si, wm_i));
                mbar_arrive(EB_AT(si, wn_i));
            }
#pragma unroll
            for (int im = 0; im < 2; im++)
#pragma unroll
                for (int in_ = 0; in_ < 8; in_++)
                    mma16816(acc[im][in_], af[im], bf[in_]);
        }
    }

    // -------- epilogue (per-warp private; no barrier needed) --------
    int row  = lane >> 2;        // 0..7
    int col2 = (lane & 3) * 2;   // 0,2,4,6
#pragma unroll
    for (int im = 0; im < 2; im++) {
        int mA = m0 + wm + im * 16 + row;
        int mB = mA + 8;
#pragma unroll
        for (int in_ = 0; in_ < 8; in_++) {
            int nl = wn + in_ * 8 + col2;   // local n within tile
            int n  = n0 + nl;
            float s0 = sS[nl], s1 = sS[nl + 1];
            float b0 = sB[nl], b1 = sB[nl + 1];
            float v0 = fmaf(s0, acc[im][in_][0], b0);
            float v1 = fmaf(s1, acc[im][in_][1], b1);
            float v2 = fmaf(s0, acc[im][in_][2], b0);
            float v3 = fmaf(s1, acc[im][in_][3], b1);
            if (TANH) {
                __half* C = reinterpret_cast<__half*>(Cout);
                *reinterpret_cast<__half2*>(C + (size_t)mA * Nld + n) =
                    __floats2half2_rn(tanh_hw(v0), tanh_hw(v1));
                *reinterpret_cast<__half2*>(C + (size_t)mB * Nld + n) =
                    __floats2half2_rn(tanh_hw(v2), tanh_hw(v3));
            } else {
                float* C = reinterpret_cast<float*>(Cout);
                *reinterpret_cast<float2*>(C + (size_t)mA * Nld + n) = make_float2(v0, v1);
                *reinterpret_cast<float2*>(C + (size_t)mB * Nld + n) = make_float2(v2, v3);
            }
        }
    }
#undef FA_AT
#undef FB_AT
#undef EA_AT
#undef EB_AT
}

extern "C" void kernel_launch(void* const* d_in, const int* in_sizes, int n_in,
                              void* d_out, int out_size) {
    const float* x  = (const float*)d_in[0];
    const float* w1 = (const float*)d_in[1];
    const float* s1 = (const float*)d_in[2];
    const float* b1 = (const float*)d_in[3];
    const float* w2 = (const float*)d_in[4];
    const float* s2 = (const float*)d_in[5];
    const float* b2 = (const float*)d_in[6];
    const float* n1 = (const float*)d_in[7];
    const float* n2 = (const float*)d_in[8];
    const float* sc = (const float*)d_in[9];
    (void)in_sizes; (void)n_in; (void)out_size;

    cudaFuncSetAttribute(gemm_tern<true>,  cudaFuncAttributeMaxDynamicSharedMemorySize, SMEM_BYTES);
    cudaFuncSetAttribute(gemm_tern<false>, cudaFuncAttributeMaxDynamicSharedMemorySize, SMEM_BYTES);

    __half *Xh, *W1t, *W2t, *H;
    cudaGetSymbolAddress((void**)&Xh,  g_Xh);
    cudaGetSymbolAddress((void**)&W1t, g_W1t);
    cudaGetSymbolAddress((void**)&W2t, g_W2t);
    cudaGetSymbolAddress((void**)&H,   g_H);

    int nquads = DIM_B * DIM_IN / 4;
    cvt_x_kernel<<<(nquads + 255) / 256, 256>>>(x, Xh, nquads);

    tern_t_kernel<<<dim3(DIM_H / 32, DIM_IN / 32), dim3(32, 8)>>>(w1, n1, sc, W1t, DIM_IN, DIM_H);
    tern_t_kernel<<<dim3(DIM_OUT / 32, DIM_H / 32), dim3(32, 8)>>>(w2, n2, sc, W2t, DIM_H, DIM_OUT);

    gemm_tern<true><<<dim3(DIM_H / BN, DIM_B / BM), NTHR, SMEM_BYTES>>>(
        Xh, W1t, s1, b1, (void*)H, DIM_H, DIM_IN);

    gemm_tern<false><<<dim3(DIM_OUT / BN, DIM_B / BM), NTHR, SMEM_BYTES>>>(
        H, W2t, s2, b2, d_out, DIM_OUT, DIM_H);
}

// round 14
// speedup vs baseline: 1.0334x; 1.0334x over previous
#include <cuda_runtime.h>
#include <cuda_fp16.h>
#include <cstdint>

#define DEV __device__ __forceinline__

// ---------------- problem dims (fixed) ----------------
static constexpr int DIM_B   = 4096;
static constexpr int DIM_IN  = 1024;
static constexpr int DIM_H   = 16384;
static constexpr int DIM_OUT = 3072;

// ---------------- GEMM tiling ----------------
// 2 CTAs/SM: 256 thr, <=128 regs, ~112 KB smem per CTA. Warp tile 32x64.
static constexpr int BM = 128, BN = 128, BK = 64, NST = 3;
static constexpr int NTHR = 256;                       // 8 warps: 4 (M) x 2 (N)
static constexpr int LDT = 72;                         // padded row length (halves)
static constexpr int ABYTES = BM * LDT * 2;            // 18432
static constexpr int BBYTES = BN * LDT * 2;            // 18432
static constexpr int STAGEB = ABYTES + BBYTES;         // 36864
static constexpr int SB_OFF = NST * STAGEB;            // 110592
static constexpr int MB_OFF = SB_OFF + 2 * BN * 4;     // 111616 (6 mbarriers)
static constexpr int SMEM_BYTES = MB_OFF + 64;         // 111680

// ---------------- scratch (device globals; allocation-free) ----------------
__device__ __align__(128) __half g_Xh [(size_t)DIM_B * DIM_IN];
__device__ __align__(128) __half g_W1t[(size_t)DIM_H * DIM_IN];     // [DH, DIN]
__device__ __align__(128) __half g_W2t[(size_t)DIM_OUT * DIM_H];    // [DOUT, DH]
__device__ __align__(128) __half g_H  [(size_t)DIM_B * DIM_H];

// ---------------- PTX helpers (baseline ISA; no sm_103a-only features) -------
DEV uint32_t s2u(const void* p) { return (uint32_t)__cvta_generic_to_shared(p); }

DEV void cp16(uint32_t dst, const void* src) {
    asm volatile("cp.async.cg.shared.global [%0], [%1], 16;" :: "r"(dst), "l"(src));
}
DEV void cp_mbar_arrive(uint32_t mb) {   // bind this thread's prior cp.asyncs to mbarrier
    asm volatile("cp.async.mbarrier.arrive.noinc.shared.b64 [%0];" :: "r"(mb) : "memory");
}
DEV void mbar_init(uint32_t mb, uint32_t cnt) {
    asm volatile("mbarrier.init.shared.b64 [%0], %1;" :: "r"(mb), "r"(cnt) : "memory");
}
DEV void mbar_arrive(uint32_t mb) {
    asm volatile("mbarrier.arrive.shared.b64 _, [%0];" :: "r"(mb) : "memory");
}
DEV void mbar_wait(uint32_t mb, uint32_t parity) {
    asm volatile(
        "{\n\t.reg .pred P;\n"
        "WAITL%=:\n\t"
        "mbarrier.try_wait.parity.acquire.cta.shared::cta.b64 P, [%0], %1;\n\t"
        "@!P bra WAITL%=;\n\t}\n"
        :: "r"(mb), "r"(parity) : "memory");
}

DEV void ldsm4(uint32_t* r, uint32_t a) {
    asm volatile("ldmatrix.sync.aligned.m8n8.x4.shared.b16 {%0,%1,%2,%3}, [%4];"
                 : "=r"(r[0]), "=r"(r[1]), "=r"(r[2]), "=r"(r[3]) : "r"(a));
}

DEV void mma16816(float* c, const uint32_t* a, const uint32_t* b) {
    asm volatile(
        "mma.sync.aligned.m16n8k16.row.col.f32.f16.f16.f32 "
        "{%0,%1,%2,%3}, {%4,%5,%6,%7}, {%8,%9}, {%0,%1,%2,%3};"
        : "+f"(c[0]), "+f"(c[1]), "+f"(c[2]), "+f"(c[3])
        : "r"(a[0]), "r"(a[1]), "r"(a[2]), "r"(a[3]), "r"(b[0]), "r"(b[1]));
}

DEV float tanh_hw(float x) {   // MUFU.TANH (sm_75+ baseline PTX)
    float y;
    asm("tanh.approx.f32 %0, %1;" : "=f"(y) : "f"(x));
    return y;
}

// scale arrives as a 4-byte scalar of unknown dtype (python int 1). Sniff bits.
DEV float load_scale(const float* p) {
    int iv = __float_as_int(*p);
    if (iv > -(1 << 24) && iv < (1 << 24)) return (float)iv;  // int bit pattern
    return __int_as_float(iv);                                 // real float bits
}

// ---------------- prepass: x -> fp16 ----------------
__global__ void cvt_x_kernel(const float* __restrict__ x, __half* __restrict__ o, int nquads) {
    int i = blockIdx.x * blockDim.x + threadIdx.x;
    if (i < nquads) {
        float4 v = *reinterpret_cast<const float4*>(x + (size_t)i * 4);
        reinterpret_cast<__half2*>(o)[2 * i + 0] = __floats2half2_rn(v.x, v.y);
        reinterpret_cast<__half2*>(o)[2 * i + 1] = __floats2half2_rn(v.z, v.w);
    }
}

// ---------------- prepass: ternarize + transpose (vectorized) ----------------
// W,NZ: [K,N] fp32 row-major.  Out[n,k] = tri(W[k,n] - sc*NZ[k,n]) fp16, [N,K].
// Tile: 128 n x 32 k.  blockDim (32,8): float4 loads (128B per warp per array).
__global__ void tern_t_kernel(const float* __restrict__ W, const float* __restrict__ NZ,
                              const float* __restrict__ scp, __half* __restrict__ Out,
                              int Kd, int Nd) {
    __shared__ __half t[128][36];          // [n][k], pad 36 (72B rows, 8B-aligned)
    float sc = load_scale(scp);
    int n0 = blockIdx.x * 128, k0 = blockIdx.y * 32;
    int tx = threadIdx.x, ty = threadIdx.y;        // 32 x 8
#pragma unroll
    for (int i = 0; i < 4; i++) {
        int k = ty + 8 * i;
        size_t gi = (size_t)(k0 + k) * Nd + n0 + 4 * tx;
        float4 w4 = *reinterpret_cast<const float4*>(W + gi);
        float4 z4 = *reinterpret_cast<const float4*>(NZ + gi);
        float q0 = w4.x - sc * z4.x, q1 = w4.y - sc * z4.y;
        float q2 = w4.z - sc * z4.z, q3 = w4.w - sc * z4.w;
        t[4 * tx + 0][k] = __float2half_rn((q0 > 1.f) ? 1.f : ((q0 < -1.f) ? -1.f : 0.f));
        t[4 * tx + 1][k] = __float2half_rn((q1 > 1.f) ? 1.f : ((q1 < -1.f) ? -1.f : 0.f));
        t[4 * tx + 2][k] = __float2half_rn((q2 > 1.f) ? 1.f : ((q2 < -1.f) ? -1.f : 0.f));
        t[4 * tx + 3][k] = __float2half_rn((q3 > 1.f) ? 1.f : ((q3 < -1.f) ? -1.f : 0.f));
    }
    __syncthreads();
    int tid = ty * 32 + tx;                 // 0..255
#pragma unroll
    for (int i = 0; i < 4; i++) {           // 1024 8B-chunks: 128 rows x 8 chunks
        int idx = tid + 256 * i;
        int r = idx >> 3;                   // n row 0..127
        int c = (idx & 7) * 4;              // k offset 0..28
        uint2 v = *reinterpret_cast<const uint2*>(&t[r][c]);   // 8B, aligned
        *reinterpret_cast<uint2*>(Out + (size_t)(n0 + r) * Kd + k0 + c) = v;
    }
}

// ---------------- GEMM stage loader (signals full[s] via mbarrier) ----------
DEV void load_stage(const __half* __restrict__ A, const __half* __restrict__ Bw,
                    int K, int m0, int n0, uint32_t base, int tid, int jt,
                    uint32_t mb_full) {
    int s  = jt % NST;
    int k0 = jt * BK;
    uint32_t sa = base + s * STAGEB;
    uint32_t sb = sa + ABYTES;
#pragma unroll
    for (int i = 0; i < 4; i++) {   // A: 1024 chunks / 256 threads
        int id = tid + i * NTHR;
        int r = id >> 3, c = (id & 7) * 8;
        cp16(sa + (uint32_t)(r * LDT + c) * 2,
             A + (size_t)(m0 + r) * K + k0 + c);
    }
#pragma unroll
    for (int i = 0; i < 4; i++) {   // B: 1024 chunks / 256 threads
        int id = tid + i * NTHR;
        int r = id >> 3, c = (id & 7) * 8;
        cp16(sb + (uint32_t)(r * LDT + c) * 2,
             Bw + (size_t)(n0 + r) * K + k0 + c);
    }
    cp_mbar_arrive(mb_full);
}

// ---------------- fused ternary GEMM (R11 pipeline, proven best) ------------
// full[s]: count=NTHR, armed by cp.async completion of all threads.
// empty[s]: count=8, armed by lane0 of each warp after MMAs of that stage.
template <bool TANH>
__global__ __launch_bounds__(NTHR, 2) void gemm_tern(
    const __half* __restrict__ A, const __half* __restrict__ Bw,
    const float* __restrict__ sv, const float* __restrict__ bv,
    void* __restrict__ Cout, int Nld, int K) {

    extern __shared__ char smem[];
    uint32_t base = s2u(smem);

    int tid = threadIdx.x, wid = tid >> 5, lane = tid & 31;
    int m0 = blockIdx.y * BM, n0 = blockIdx.x * BN;
    int wm = (wid & 3) * 32;   // warp M offset (4 warps along M)
    int wn = (wid >> 2) * 64;  // warp N offset (2 warps along N)

    uint32_t mb_full0  = base + MB_OFF;        // full[0..2] at +0,+8,+16
    uint32_t mb_empty0 = base + MB_OFF + 24;   // empty[0..2] at +24,+32,+40

    float* sS = reinterpret_cast<float*>(smem + SB_OFF);
    float* sB = sS + BN;
    for (int i = tid; i < BN; i += NTHR) { sS[i] = sv[n0 + i]; sB[i] = bv[n0 + i]; }

    if (tid == 0) {
#pragma unroll
        for (int s = 0; s < NST; s++) {
            mbar_init(mb_full0 + s * 8, NTHR);
            mbar_init(mb_empty0 + s * 8, 8);
        }
    }
    __syncthreads();   // mbarrier init + sS/sB visible to all

    // per-lane ldmatrix byte offsets within a stage (A at +0, B at +ABYTES)
    uint32_t aoff[2];
#pragma unroll
    for (int im = 0; im < 2; im++)
        aoff[im] = (uint32_t)((wm + im * 16 + (lane & 15)) * LDT + (lane >> 4) * 8) * 2;
    uint32_t boff[4];
    {
        int g = lane >> 3;
#pragma unroll
        for (int p = 0; p < 4; p++)
            boff[p] = (uint32_t)(ABYTES) +
                      (uint32_t)((wn + p * 16 + (g >> 1) * 8 + (lane & 7)) * LDT + (g & 1) * 8) * 2;
    }

    const int KT = K / BK;
    load_stage(A, Bw, K, m0, n0, base, tid, 0, mb_full0 + 0 * 8);
    load_stage(A, Bw, K, m0, n0, base, tid, 1, mb_full0 + 1 * 8);

    float acc[2][8][4];
#pragma unroll
    for (int im = 0; im < 2; im++)
#pragma unroll
        for (int in_ = 0; in_ < 8; in_++)
#pragma unroll
            for (int r = 0; r < 4; r++) acc[im][in_][r] = 0.0f;

    for (int it = 0; it < KT; ++it) {
        int jt = it + 2;                       // prefetch distance 2, 3 slots
        if (jt < KT) {
            int sj = jt - (jt / NST) * NST;
            if (jt >= NST)                      // slot reused: wait consumption of jt-3
                mbar_wait(mb_empty0 + sj * 8, (uint32_t)(((jt / NST) - 1) & 1));
            load_stage(A, Bw, K, m0, n0, base, tid, jt, mb_full0 + sj * 8);
        }

        int si = it - (it / NST) * NST;
        mbar_wait(mb_full0 + si * 8, (uint32_t)((it / NST) & 1));   // data ready

        uint32_t sbase = base + (uint32_t)si * STAGEB;
#pragma unroll
        for (int ks = 0; ks < 4; ks++) {
            uint32_t kb = (uint32_t)(ks * 16 * 2);
            uint32_t af[2][4], bf[8][2];
#pragma unroll
            for (int im = 0; im < 2; im++)
                ldsm4(af[im], sbase + aoff[im] + kb);
#pragma unroll
            for (int p = 0; p < 4; p++) {
                uint32_t r4[4];
                ldsm4(r4, sbase + boff[p] + kb);
                bf[2 * p][0] = r4[0]; bf[2 * p][1] = r4[1];
                bf[2 * p + 1][0] = r4[2]; bf[2 * p + 1][1] = r4[3];
            }
#pragma unroll
            for (int im = 0; im < 2; im++)
#pragma unroll
                for (int in_ = 0; in_ < 8; in_++)
                    mma16816(acc[im][in_], af[im], bf[in_]);
        }
        if (lane == 0) mbar_arrive(mb_empty0 + si * 8);   // this warp done with stage
    }

    // -------- epilogue (per-warp private; no barrier needed) --------
    int row  = lane >> 2;        // 0..7
    int col2 = (lane & 3) * 2;   // 0,2,4,6
#pragma unroll
    for (int im = 0; im < 2; im++) {
        int mA = m0 + wm + im * 16 + row;
        int mB = mA + 8;
#pragma unroll
        for (int in_ = 0; in_ < 8; in_++) {
            int nl = wn + in_ * 8 + col2;   // local n within tile
            int n  = n0 + nl;
            float s0 = sS[nl], s1 = sS[nl + 1];
            float b0 = sB[nl], b1 = sB[nl + 1];
            float v0 = fmaf(s0, acc[im][in_][0], b0);
            float v1 = fmaf(s1, acc[im][in_][1], b1);
            float v2 = fmaf(s0, acc[im][in_][2], b0);
            float v3 = fmaf(s1, acc[im][in_][3], b1);
            if (TANH) {
                __half* C = reinterpret_cast<__half*>(Cout);
                *reinterpret_cast<__half2*>(C + (size_t)mA * Nld + n) =
                    __floats2half2_rn(tanh_hw(v0), tanh_hw(v1));
                *reinterpret_cast<__half2*>(C + (size_t)mB * Nld + n) =
                    __floats2half2_rn(tanh_hw(v2), tanh_hw(v3));
            } else {
                float* C = reinterpret_cast<float*>(Cout);
                *reinterpret_cast<float2*>(C + (size_t)mA * Nld + n) = make_float2(v0, v1);
                *reinterpret_cast<float2*>(C + (size_t)mB * Nld + n) = make_float2(v2, v3);
            }
        }
    }
}

extern "C" void kernel_launch(void* const* d_in, const int* in_sizes, int n_in,
                              void* d_out, int out_size) {
    const float* x  = (const float*)d_in[0];
    const float* w1 = (const float*)d_in[1];
    const float* s1 = (const float*)d_in[2];
    const float* b1 = (const float*)d_in[3];
    const float* w2 = (const float*)d_in[4];
    const float* s2 = (const float*)d_in[5];
    const float* b2 = (const float*)d_in[6];
    const float* n1 = (const float*)d_in[7];
    const float* n2 = (const float*)d_in[8];
    const float* sc = (const float*)d_in[9];
    (void)in_sizes; (void)n_in; (void)out_size;

    cudaFuncSetAttribute(gemm_tern<true>,  cudaFuncAttributeMaxDynamicSharedMemorySize, SMEM_BYTES);
    cudaFuncSetAttribute(gemm_tern<false>, cudaFuncAttributeMaxDynamicSharedMemorySize, SMEM_BYTES);

    __half *Xh, *W1t, *W2t, *H;
    cudaGetSymbolAddress((void**)&Xh,  g_Xh);
    cudaGetSymbolAddress((void**)&W1t, g_W1t);
    cudaGetSymbolAddress((void**)&W2t, g_W2t);
    cudaGetSymbolAddress((void**)&H,   g_H);

    int nquads = DIM_B * DIM_IN / 4;
    cvt_x_kernel<<<(nquads + 255) / 256, 256>>>(x, Xh, nquads);

    tern_t_kernel<<<dim3(DIM_H / 128, DIM_IN / 32), dim3(32, 8)>>>(w1, n1, sc, W1t, DIM_IN, DIM_H);
    tern_t_kernel<<<dim3(DIM_OUT / 128, DIM_H / 32), dim3(32, 8)>>>(w2, n2, sc, W2t, DIM_H, DIM_OUT);

    gemm_tern<true><<<dim3(DIM_H / BN, DIM_B / BM), NTHR, SMEM_BYTES>>>(
        Xh, W1t, s1, b1, (void*)H, DIM_H, DIM_IN);

    gemm_tern<false><<<dim3(DIM_OUT / BN, DIM_B / BM), NTHR, SMEM_BYTES>>>(
        H, W2t, s2, b2, d_out, DIM_OUT, DIM_H);
}